// round 1
// baseline (speedup 1.0000x reference)
#include <cuda_runtime.h>
#include <math.h>
#include <stdint.h>
#include <stddef.h>

#define NRAYS 2048
#define NSAMP 128
#define NS (NRAYS * NSAMP)   // 262144 samples per pass

// ---------------- static scratch (no allocations allowed) ----------------
__device__ float g_enc[NS * 96];        // IPE encodings
__device__ float g_x0[NS * 256];        // activation ping
__device__ float g_x1[NS * 256];        // activation pong
__device__ float g_h [NS * 128];        // post-Wd hidden
__device__ float g_rf[NS * 6];          // raw heads: rgb(3), sigma, mu_raw-ish, sig_raw-ish
__device__ float g_direnc[NRAYS * 27];
__device__ float g_raynorm[NRAYS];
__device__ float g_raybias[NRAYS * 128];
__device__ float g_weights[NS];
__device__ float g_mus[NS];
__device__ float g_smsig[NS];
__device__ float g_lt[NS];
__device__ float g_pib[NS];
__device__ float g_tfine[NRAYS * 129];

// ---------------- helpers ----------------
__device__ __forceinline__ float sigmoidf_(float x) {
    return 1.0f / (1.0f + expf(-x));
}
__device__ __forceinline__ float acdf_(float x) {
    // 0.5*(1+tanh(sqrt(2/pi)*(x+0.044715 x^3)))
    float x3 = x * x * x;
    return 0.5f * (1.0f + tanhf(0.7978845608028654f * (x + 0.044715f * x3)));
}

// ---------------- ray setup: viewdirs + dir encoding + |rd| ----------------
__global__ void ray_setup_kernel(const float* __restrict__ rd) {
    int r = blockIdx.x * blockDim.x + threadIdx.x;
    if (r >= NRAYS) return;
    float x = rd[r * 3 + 0], y = rd[r * 3 + 1], z = rd[r * 3 + 2];
    float n = sqrtf(x * x + y * y + z * z);
    g_raynorm[r] = n;
    float inv = 1.0f / n;
    float v[3] = {x * inv, y * inv, z * inv};
    float* de = g_direnc + r * 27;
    de[0] = v[0]; de[1] = v[1]; de[2] = v[2];
#pragma unroll
    for (int f = 0; f < 4; f++) {
        float fr = (float)(1 << f);
#pragma unroll
        for (int k = 0; k < 3; k++) {
            float xx = v[k] * fr;
            de[3 + f * 3 + k]  = sinf(xx);
            de[15 + f * 3 + k] = cosf(xx);
        }
    }
}

// per-ray bias for the Wd layer: bd[o] + sum_j direnc[j] * Wd[256+j][o]
__global__ void ray_bias_kernel(const float* __restrict__ Wd, const float* __restrict__ bd) {
    int r = blockIdx.x;
    int o = threadIdx.x;   // 0..127
    __shared__ float de[27];
    if (o < 27) de[o] = g_direnc[r * 27 + o];
    __syncthreads();
    float a = bd[o];
#pragma unroll
    for (int j = 0; j < 27; j++) a += de[j] * Wd[(256 + j) * 128 + o];
    g_raybias[r * 128 + o] = a;
}

// ---------------- cast_rays + integrated positional encoding ----------------
__global__ void ipe_kernel(const float* __restrict__ ro, const float* __restrict__ rd,
                           const float* __restrict__ rr, const float* __restrict__ tsrc) {
    int s = blockIdx.x * blockDim.x + threadIdx.x;
    if (s >= NS) return;
    int ray = s >> 7, i = s & 127;
    float t0, t1;
    if (tsrc) {
        t0 = tsrc[ray * 129 + i];
        t1 = tsrc[ray * 129 + i + 1];
    } else {
        t0 = 2.0f + 4.0f * ((float)i / 128.0f);
        t1 = 2.0f + 4.0f * ((float)(i + 1) / 128.0f);
    }
    float c  = 0.5f * (t0 + t1);
    float dd = 0.5f * (t1 - t0);
    float d2s = dd * dd;
    float d4  = d2s * d2s;
    float c2  = c * c;
    float denom = 3.0f * c2 + d2s;
    float t_mean = c + 2.0f * c * d2s / denom;
    float t_var  = d2s * (1.0f / 3.0f) - (4.0f / 15.0f) * (d4 * (12.0f * c2 - d2s)) / (denom * denom);
    float rrv = rr[ray];
    float r_var = rrv * rrv * (c2 * 0.25f + (5.0f / 12.0f) * d2s - (4.0f / 15.0f) * d4 / denom);

    float rdv[3] = {rd[ray * 3 + 0], rd[ray * 3 + 1], rd[ray * 3 + 2]};
    float rov[3] = {ro[ray * 3 + 0], ro[ray * 3 + 1], ro[ray * 3 + 2]};
    float dn2 = rdv[0] * rdv[0] + rdv[1] * rdv[1] + rdv[2] * rdv[2];
    float invd2 = 1.0f / fmaxf(dn2, 1e-10f);
    float mean[3], cov[3];
#pragma unroll
    for (int k = 0; k < 3; k++) {
        mean[k] = rov[k] + rdv[k] * t_mean;
        float dok = rdv[k] * rdv[k];
        cov[k] = t_var * dok + r_var * (1.0f - dok * invd2);
    }

    float* e = g_enc + (size_t)s * 96;
    float scale = 1.0f;
#pragma unroll 4
    for (int deg = 0; deg < 16; deg++) {
        float sc2 = scale * scale;
#pragma unroll
        for (int k = 0; k < 3; k++) {
            int idx = deg * 3 + k;
            float yv = cov[k] * sc2;
            if (yv > 60.0f) {           // att < 1e-13, contribution negligible
                e[idx] = 0.0f;
                e[48 + idx] = 0.0f;
            } else {
                float att = expf(-0.5f * yv);
                float y = mean[k] * scale;
                // accurate range reduction (y can reach ~1e5 at high degrees)
                double kd = rint((double)y * 0.15915494309189535);  // y / (2*pi)
                float rp = (float)((double)y - kd * 6.283185307179586);
                float sy, cy;
                sincosf(rp, &sy, &cy);
                e[idx]      = sy * att;
                e[48 + idx] = cy * att;
            }
        }
        scale *= 2.0f;
    }
}

// ---------------- fp32 SGEMM: C[M,N] = act(A[M,K] @ W[K,N] + bias) ----------------
// BM=BN=128, BK=8, 256 threads, 8x8 micro-tile. M=262144, K%8==0, N%128==0.
template<bool RELU, bool RAYBIAS>
__global__ void __launch_bounds__(256) sgemm_kernel(
    const float* __restrict__ A, const float* __restrict__ W,
    const float* __restrict__ bias, float* __restrict__ C,
    int K, int N)
{
    __shared__ float As[8][128];
    __shared__ float Bs[8][128];
    const int tid = threadIdx.x;
    const int bm = blockIdx.x * 128;
    const int bn = blockIdx.y * 128;
    const int tx = tid & 15;
    const int ty = tid >> 4;
    const int arow = tid >> 1;
    const int acol = (tid & 1) * 4;
    const int wrow = tid >> 5;
    const int wcol = (tid & 31) * 4;

    const float* Ap = A + (size_t)(bm + arow) * K + acol;
    const float* Wp = W + (size_t)wrow * N + (bn + wcol);

    float acc[8][8];
#pragma unroll
    for (int i = 0; i < 8; i++)
#pragma unroll
        for (int j = 0; j < 8; j++) acc[i][j] = 0.0f;

    float4 av = *(const float4*)Ap;
    float4 wv = *(const float4*)Wp;
    const int nIter = K >> 3;

    for (int it = 0; it < nIter; ++it) {
        As[acol + 0][arow] = av.x;
        As[acol + 1][arow] = av.y;
        As[acol + 2][arow] = av.z;
        As[acol + 3][arow] = av.w;
        *(float4*)&Bs[wrow][wcol] = wv;
        __syncthreads();

        Ap += 8;
        Wp += (size_t)8 * N;
        if (it + 1 < nIter) {
            av = *(const float4*)Ap;
            wv = *(const float4*)Wp;
        }

#pragma unroll
        for (int k = 0; k < 8; k++) {
            float4 a0 = *(const float4*)&As[k][ty * 8];
            float4 a1 = *(const float4*)&As[k][ty * 8 + 4];
            float4 b0 = *(const float4*)&Bs[k][tx * 8];
            float4 b1 = *(const float4*)&Bs[k][tx * 8 + 4];
            float ar[8] = {a0.x, a0.y, a0.z, a0.w, a1.x, a1.y, a1.z, a1.w};
            float br_[8] = {b0.x, b0.y, b0.z, b0.w, b1.x, b1.y, b1.z, b1.w};
#pragma unroll
            for (int i = 0; i < 8; i++)
#pragma unroll
                for (int j = 0; j < 8; j++)
                    acc[i][j] += ar[i] * br_[j];
        }
        __syncthreads();
    }

#pragma unroll
    for (int i = 0; i < 8; i++) {
        int row = bm + ty * 8 + i;
#pragma unroll
        for (int j = 0; j < 8; j++) {
            int col = bn + tx * 8 + j;
            float bv = RAYBIAS ? bias[(size_t)(row >> 7) * N + col] : bias[col];
            float v = acc[i][j] + bv;
            if (RELU) v = fmaxf(v, 0.0f);
            C[(size_t)row * N + col] = v;
        }
    }
}

// ---------------- thin heads: sigma(256->1), [mu,sig](256->2), rgb(128->3) ----------------
__global__ void __launch_bounds__(256) heads_kernel(
    const float* __restrict__ X3, const float* __restrict__ H,
    const float* __restrict__ Ws, const float* __restrict__ bs,
    const float* __restrict__ Wm, const float* __restrict__ bm,
    const float* __restrict__ Wr, const float* __restrict__ br,
    float* __restrict__ RF)
{
    int gw = (blockIdx.x * 256 + threadIdx.x) >> 5;
    int lane = threadIdx.x & 31;
    if (gw >= NS) return;
    const bool hasM = (Wm != nullptr);
    const float* x = X3 + (size_t)gw * 256;
    float s0 = 0.0f, s1 = 0.0f, s2 = 0.0f;
#pragma unroll
    for (int i = 0; i < 8; i++) {
        int c = lane + 32 * i;
        float xv = x[c];
        s0 += xv * Ws[c];
        if (hasM) {
            s1 += xv * Wm[2 * c];
            s2 += xv * Wm[2 * c + 1];
        }
    }
    const float* h = H + (size_t)gw * 128;
    float r = 0.0f, g = 0.0f, b = 0.0f;
#pragma unroll
    for (int i = 0; i < 4; i++) {
        int c = lane + 32 * i;
        float hv = h[c];
        r += hv * Wr[3 * c];
        g += hv * Wr[3 * c + 1];
        b += hv * Wr[3 * c + 2];
    }
#pragma unroll
    for (int o = 16; o > 0; o >>= 1) {
        s0 += __shfl_down_sync(0xffffffffu, s0, o);
        s1 += __shfl_down_sync(0xffffffffu, s1, o);
        s2 += __shfl_down_sync(0xffffffffu, s2, o);
        r  += __shfl_down_sync(0xffffffffu, r, o);
        g  += __shfl_down_sync(0xffffffffu, g, o);
        b  += __shfl_down_sync(0xffffffffu, b, o);
    }
    if (lane == 0) {
        float* f = RF + (size_t)gw * 6;
        f[0] = r + br[0];
        f[1] = g + br[1];
        f[2] = b + br[2];
        f[3] = s0 + bs[0];
        if (hasM) {
            f[4] = s1 + bm[0];
            f[5] = s2 + bm[1];
        }
    }
}

// ---------------- coarse volume render + PDF ingredients ----------------
__global__ void vrender_coarse_kernel(float* __restrict__ out) {
    int r = blockIdx.x * blockDim.x + threadIdx.x;
    if (r >= NRAYS) return;
    float nrm = g_raynorm[r];
    float T = 1.0f, cr = 0.0f, cg = 0.0f, cb = 0.0f;
    for (int i = 0; i < 128; i++) {
        const float* f = g_rf + (size_t)(r * 128 + i) * 6;
        float t0 = 2.0f + 4.0f * ((float)i / 128.0f);
        float t1 = 2.0f + 4.0f * ((float)(i + 1) / 128.0f);
        float sr = sigmoidf_(f[0]);
        float sg = sigmoidf_(f[1]);
        float sb = sigmoidf_(f[2]);
        float sigma = fmaxf(f[3], 0.0f);
        float alpha = 1.0f - expf(-sigma * (t1 - t0) * nrm);
        float w = alpha * T;
        T *= (1.0f - alpha + 1e-10f);
        cr += w * sr; cg += w * sg; cb += w * sb;
        int si = r * 128 + i;
        g_weights[si] = w;
        float mu = sigmoidf_(f[4]);
        float ss = (sigmoidf_(f[5]) + 0.001f) * 2.0f;   // sigmas * SMOOTH
        g_mus[si] = mu;
        g_smsig[si] = ss;
        float l = acdf_((0.0f - mu) / ss);
        g_lt[si] = l;
        g_pib[si] = acdf_((1.0f - mu) / ss) - l;
    }
    out[r * 3 + 0] = cr;
    out[r * 3 + 1] = cg;
    out[r * 3 + 2] = cb;
}

// ---------------- inverse-CDF fine sampling (output already monotone) ----------------
__global__ void sample_pdf_kernel() {
    int r = blockIdx.x * blockDim.x + threadIdx.x;
    if (r >= NRAYS) return;
    float wl[128];
    float cdf[129];
    float sum = 0.0f;
    for (int i = 0; i < 128; i++) {
        float w = g_weights[r * 128 + i] + 1e-5f;
        wl[i] = w;
        sum += w;
    }
    float inv = 1.0f / sum;
    cdf[0] = 0.0f;
    float run = 0.0f;
    for (int i = 0; i < 128; i++) {
        run += wl[i] * inv;
        cdf[i + 1] = run;
    }
    int idx = 0;
    const float step = (1.0f - 1e-5f) / 128.0f;
    for (int i = 0; i < 129; i++) {
        float u = step * (float)i;
        while (idx < 127 && cdf[idx + 1] <= u) idx++;
        float pdfv = wl[idx] * inv;
        float frac = (u - cdf[idx]) / fmaxf(pdfv, 1e-10f);
        frac = fminf(fmaxf(frac, 0.0f), 1.0f);
        int si = r * 128 + idx;
        float p = g_lt[si] + frac * g_pib[si];
        p = fminf(fmaxf(p, 1e-5f), 1.0f - 1e-5f);
        float x = g_mus[si] + g_smsig[si] * 1.4142135623730951f * erfinvf(2.0f * p - 1.0f);
        x = fminf(fmaxf(x, 0.0f), 1.0f);
        float b0 = 2.0f + 4.0f * ((float)idx / 128.0f);
        float b1 = 2.0f + 4.0f * ((float)(idx + 1) / 128.0f);
        g_tfine[r * 129 + i] = b0 + x * (b1 - b0);
    }
}

// ---------------- fine volume render: rgb_f, depth_f, acc_f ----------------
__global__ void vrender_fine_kernel(float* __restrict__ out) {
    int r = blockIdx.x * blockDim.x + threadIdx.x;
    if (r >= NRAYS) return;
    float nrm = g_raynorm[r];
    float T = 1.0f, cr = 0.0f, cg = 0.0f, cb = 0.0f, dep = 0.0f, acc = 0.0f;
    for (int i = 0; i < 128; i++) {
        const float* f = g_rf + (size_t)(r * 128 + i) * 6;
        float t0 = g_tfine[r * 129 + i];
        float t1 = g_tfine[r * 129 + i + 1];
        float sr = sigmoidf_(f[0]);
        float sg = sigmoidf_(f[1]);
        float sb = sigmoidf_(f[2]);
        float sigma = fmaxf(f[3], 0.0f);
        float alpha = 1.0f - expf(-sigma * (t1 - t0) * nrm);
        float w = alpha * T;
        T *= (1.0f - alpha + 1e-10f);
        cr += w * sr; cg += w * sg; cb += w * sb;
        dep += w * 0.5f * (t0 + t1);
        acc += w;
    }
    out[6144 + r * 3 + 0] = cr;
    out[6144 + r * 3 + 1] = cg;
    out[6144 + r * 3 + 2] = cb;
    out[12288 + r] = dep;
    out[14336 + r] = acc;
}

// ---------------- host orchestration ----------------
extern "C" void kernel_launch(void* const* d_in, const int* in_sizes, int n_in,
                              void* d_out, int out_size)
{
    (void)out_size;
    const float* ro = (const float*)d_in[0];
    const float* rd = (const float*)d_in[1];
    const float* rr = (const float*)d_in[2];

    // Detect ordering: signature order puts cWm (256*2=512) at index 15;
    // setup_inputs dict order puts fW0 (96*256=24576) there.
    bool sigOrder = (n_in > 15 && in_sizes[15] == 512);
    int fb = sigOrder ? 17 : 15;
    int mb = sigOrder ? 15 : 27;

    const float* cW0 = (const float*)d_in[3];
    const float* cb0 = (const float*)d_in[4];
    const float* cWh = (const float*)d_in[5];
    const float* cbh = (const float*)d_in[6];
    const float* cWs = (const float*)d_in[7];
    const float* cbs = (const float*)d_in[8];
    const float* cWb = (const float*)d_in[9];
    const float* cbb = (const float*)d_in[10];
    const float* cWd = (const float*)d_in[11];
    const float* cbd = (const float*)d_in[12];
    const float* cWr = (const float*)d_in[13];
    const float* cbr = (const float*)d_in[14];
    const float* cWm = (const float*)d_in[mb];
    const float* cbm = (const float*)d_in[mb + 1];
    const float* fW0 = (const float*)d_in[fb + 0];
    const float* fb0 = (const float*)d_in[fb + 1];
    const float* fWh = (const float*)d_in[fb + 2];
    const float* fbh = (const float*)d_in[fb + 3];
    const float* fWs = (const float*)d_in[fb + 4];
    const float* fbs = (const float*)d_in[fb + 5];
    const float* fWb = (const float*)d_in[fb + 6];
    const float* fbb = (const float*)d_in[fb + 7];
    const float* fWd = (const float*)d_in[fb + 8];
    const float* fbd = (const float*)d_in[fb + 9];
    const float* fWr = (const float*)d_in[fb + 10];
    const float* fbr = (const float*)d_in[fb + 11];

    float *p_enc, *p_x0, *p_x1, *p_h, *p_rf, *p_raybias, *p_tfine;
    cudaGetSymbolAddress((void**)&p_enc, g_enc);
    cudaGetSymbolAddress((void**)&p_x0, g_x0);
    cudaGetSymbolAddress((void**)&p_x1, g_x1);
    cudaGetSymbolAddress((void**)&p_h, g_h);
    cudaGetSymbolAddress((void**)&p_rf, g_rf);
    cudaGetSymbolAddress((void**)&p_raybias, g_raybias);
    cudaGetSymbolAddress((void**)&p_tfine, g_tfine);

    float* out = (float*)d_out;
    const dim3 gWide(NS / 128, 2);   // N=256 layers
    const dim3 gNarrow(NS / 128, 1); // N=128 layer

    ray_setup_kernel<<<(NRAYS + 127) / 128, 128>>>(rd);

    // ================= coarse pass =================
    ipe_kernel<<<NS / 128, 128>>>(ro, rd, rr, nullptr);
    ray_bias_kernel<<<NRAYS, 128>>>(cWd, cbd);
    sgemm_kernel<true, false><<<gWide, 256>>>(p_enc, cW0, cb0, p_x0, 96, 256);
    sgemm_kernel<true, false><<<gWide, 256>>>(p_x0, cWh,           cbh,       p_x1, 256, 256);
    sgemm_kernel<true, false><<<gWide, 256>>>(p_x1, cWh + 65536,   cbh + 256, p_x0, 256, 256);
    sgemm_kernel<true, false><<<gWide, 256>>>(p_x0, cWh + 131072,  cbh + 512, p_x1, 256, 256);
    sgemm_kernel<false, false><<<gWide, 256>>>(p_x1, cWb, cbb, p_x0, 256, 256);
    sgemm_kernel<true, true><<<gNarrow, 256>>>(p_x0, cWd, p_raybias, p_h, 256, 128);
    heads_kernel<<<NS / 8, 256>>>(p_x1, p_h, cWs, cbs, cWm, cbm, cWr, cbr, p_rf);
    vrender_coarse_kernel<<<(NRAYS + 127) / 128, 128>>>(out);
    sample_pdf_kernel<<<(NRAYS + 127) / 128, 128>>>();

    // ================= fine pass =================
    ipe_kernel<<<NS / 128, 128>>>(ro, rd, rr, p_tfine);
    ray_bias_kernel<<<NRAYS, 128>>>(fWd, fbd);
    sgemm_kernel<true, false><<<gWide, 256>>>(p_enc, fW0, fb0, p_x0, 96, 256);
    sgemm_kernel<true, false><<<gWide, 256>>>(p_x0, fWh,           fbh,       p_x1, 256, 256);
    sgemm_kernel<true, false><<<gWide, 256>>>(p_x1, fWh + 65536,   fbh + 256, p_x0, 256, 256);
    sgemm_kernel<true, false><<<gWide, 256>>>(p_x0, fWh + 131072,  fbh + 512, p_x1, 256, 256);
    sgemm_kernel<false, false><<<gWide, 256>>>(p_x1, fWb, fbb, p_x0, 256, 256);
    sgemm_kernel<true, true><<<gNarrow, 256>>>(p_x0, fWd, p_raybias, p_h, 256, 128);
    heads_kernel<<<NS / 8, 256>>>(p_x1, p_h, fWs, fbs, nullptr, nullptr, fWr, fbr, p_rf);
    vrender_fine_kernel<<<(NRAYS + 127) / 128, 128>>>(out);
}

// round 3
// speedup vs baseline: 1.3950x; 1.3950x over previous
#include <cuda_runtime.h>
#include <math.h>
#include <stdint.h>
#include <stddef.h>

#define NRAYS 2048
#define NSAMP 128
#define NS (NRAYS * NSAMP)   // 262144 samples per pass

// ---------------- static scratch (no allocations allowed) ----------------
__device__ float g_enc[NS * 96];        // IPE encodings
__device__ float g_x0[NS * 256];        // activation ping
__device__ float g_x1[NS * 256];        // activation pong
__device__ float g_h [NS * 128];        // post-Wd hidden
__device__ float g_rf[NS * 6];          // raw heads
__device__ float g_direnc[NRAYS * 27];
__device__ float g_raynorm[NRAYS];
__device__ float g_raybias[NRAYS * 128];
__device__ float g_weights[NS];
__device__ float g_mus[NS];
__device__ float g_smsig[NS];
__device__ float g_lt[NS];
__device__ float g_pib[NS];
__device__ float g_tfine[NRAYS * 129];

// ---------------- helpers ----------------
__device__ __forceinline__ float sigmoidf_(float x) {
    return 1.0f / (1.0f + expf(-x));
}
__device__ __forceinline__ float acdf_(float x) {
    float x3 = x * x * x;
    return 0.5f * (1.0f + tanhf(0.7978845608028654f * (x + 0.044715f * x3)));
}
__device__ __forceinline__ uint32_t f2tf32(float x) {
    uint32_t r;
    asm("cvt.rna.tf32.f32 %0, %1;" : "=r"(r) : "f"(x));
    return r;
}

#define MMA_TF32(d, a0, a1, a2, a3, b0, b1)                                  \
    asm volatile(                                                            \
        "mma.sync.aligned.m16n8k8.row.col.f32.tf32.tf32.f32 "                \
        "{%0,%1,%2,%3}, {%4,%5,%6,%7}, {%8,%9}, {%0,%1,%2,%3};"              \
        : "+f"(d[0]), "+f"(d[1]), "+f"(d[2]), "+f"(d[3])                     \
        : "r"(a0), "r"(a1), "r"(a2), "r"(a3), "r"(b0), "r"(b1))

// ---------------- ray setup: viewdirs + dir encoding + |rd| ----------------
__global__ void ray_setup_kernel(const float* __restrict__ rd) {
    int r = blockIdx.x * blockDim.x + threadIdx.x;
    if (r >= NRAYS) return;
    float x = rd[r * 3 + 0], y = rd[r * 3 + 1], z = rd[r * 3 + 2];
    float n = sqrtf(x * x + y * y + z * z);
    g_raynorm[r] = n;
    float inv = 1.0f / n;
    float v[3] = {x * inv, y * inv, z * inv};
    float* de = g_direnc + r * 27;
    de[0] = v[0]; de[1] = v[1]; de[2] = v[2];
#pragma unroll
    for (int f = 0; f < 4; f++) {
        float fr = (float)(1 << f);
#pragma unroll
        for (int k = 0; k < 3; k++) {
            float xx = v[k] * fr;
            de[3 + f * 3 + k]  = sinf(xx);
            de[15 + f * 3 + k] = cosf(xx);
        }
    }
}

// per-ray bias for the Wd layer: bd[o] + sum_j direnc[j] * Wd[256+j][o]
__global__ void ray_bias_kernel(const float* __restrict__ Wd, const float* __restrict__ bd) {
    int r = blockIdx.x;
    int o = threadIdx.x;   // 0..127
    __shared__ float de[27];
    if (o < 27) de[o] = g_direnc[r * 27 + o];
    __syncthreads();
    float a = bd[o];
#pragma unroll
    for (int j = 0; j < 27; j++) a += de[j] * Wd[(256 + j) * 128 + o];
    g_raybias[r * 128 + o] = a;
}

// ---------------- cast_rays + integrated positional encoding ----------------
__global__ void ipe_kernel(const float* __restrict__ ro, const float* __restrict__ rd,
                           const float* __restrict__ rr, const float* __restrict__ tsrc) {
    int s = blockIdx.x * blockDim.x + threadIdx.x;
    if (s >= NS) return;
    int ray = s >> 7, i = s & 127;
    float t0, t1;
    if (tsrc) {
        t0 = tsrc[ray * 129 + i];
        t1 = tsrc[ray * 129 + i + 1];
    } else {
        t0 = 2.0f + 4.0f * ((float)i / 128.0f);
        t1 = 2.0f + 4.0f * ((float)(i + 1) / 128.0f);
    }
    float c  = 0.5f * (t0 + t1);
    float dd = 0.5f * (t1 - t0);
    float d2s = dd * dd;
    float d4  = d2s * d2s;
    float c2  = c * c;
    float denom = 3.0f * c2 + d2s;
    float t_mean = c + 2.0f * c * d2s / denom;
    float t_var  = d2s * (1.0f / 3.0f) - (4.0f / 15.0f) * (d4 * (12.0f * c2 - d2s)) / (denom * denom);
    float rrv = rr[ray];
    float r_var = rrv * rrv * (c2 * 0.25f + (5.0f / 12.0f) * d2s - (4.0f / 15.0f) * d4 / denom);

    float rdv[3] = {rd[ray * 3 + 0], rd[ray * 3 + 1], rd[ray * 3 + 2]};
    float rov[3] = {ro[ray * 3 + 0], ro[ray * 3 + 1], ro[ray * 3 + 2]};
    float dn2 = rdv[0] * rdv[0] + rdv[1] * rdv[1] + rdv[2] * rdv[2];
    float invd2 = 1.0f / fmaxf(dn2, 1e-10f);
    float mean[3], cov[3];
#pragma unroll
    for (int k = 0; k < 3; k++) {
        mean[k] = rov[k] + rdv[k] * t_mean;
        float dok = rdv[k] * rdv[k];
        cov[k] = t_var * dok + r_var * (1.0f - dok * invd2);
    }

    float* e = g_enc + (size_t)s * 96;
    float scale = 1.0f;
#pragma unroll 4
    for (int deg = 0; deg < 16; deg++) {
        float sc2 = scale * scale;
#pragma unroll
        for (int k = 0; k < 3; k++) {
            int idx = deg * 3 + k;
            float yv = cov[k] * sc2;
            if (yv > 60.0f) {
                e[idx] = 0.0f;
                e[48 + idx] = 0.0f;
            } else {
                float att = expf(-0.5f * yv);
                float y = mean[k] * scale;
                double kd = rint((double)y * 0.15915494309189535);
                float rp = (float)((double)y - kd * 6.283185307179586);
                float sy, cy;
                sincosf(rp, &sy, &cy);
                e[idx]      = sy * att;
                e[48 + idx] = cy * att;
            }
        }
        scale *= 2.0f;
    }
}

// ---------------- tf32x3 tensor-core GEMM ----------------
// C[M,N] = act(A[M,K] @ W[K,N] + bias). A row-major, W row-major, C row-major.
// BM=BN=128, BK=8, 256 threads, 8 warps as 4(m)x2(n), warp tile 32x64.
// 3xTF32 split: a = hi + lo (tf32 each); d += aH*bH + aL*bH + aH*bL.
template<bool RELU, bool RAYBIAS>
__global__ void __launch_bounds__(256, 2) sgemm_tc(
    const float* __restrict__ A, const float* __restrict__ W,
    const float* __restrict__ bias, float* __restrict__ C,
    int K, int N)
{
    // padded stride 136: bank = 8*k + group -> conflict-free fragment loads
    __shared__ uint32_t AsH[2][8][136];
    __shared__ uint32_t AsL[2][8][136];
    __shared__ uint32_t BsH[2][8][136];
    __shared__ uint32_t BsL[2][8][136];

    const int tid  = threadIdx.x;
    const int bm   = blockIdx.x * 128;
    const int bn   = blockIdx.y * 128;
    const int wid  = tid >> 5;
    const int lane = tid & 31;
    const int wm   = (wid & 3) * 32;   // warp m offset in tile
    const int wn   = (wid >> 2) * 64;  // warp n offset in tile
    const int g    = lane >> 2;        // group 0..7
    const int t4   = lane & 3;         // thread in group

    // global load mapping
    const int ar = tid >> 1;          // A row 0..127
    const int ac = (tid & 1) * 4;     // A col group {0,4}
    const int br = tid >> 5;          // B row 0..7
    const int bc = (tid & 31) * 4;    // B col 0..124

    const float* Ap = A + (size_t)(bm + ar) * K + ac;
    const float* Wp = W + (size_t)br * N + bn + bc;

    float d[2][8][4];
#pragma unroll
    for (int mt = 0; mt < 2; mt++)
#pragma unroll
        for (int nt = 0; nt < 8; nt++)
#pragma unroll
            for (int q = 0; q < 4; q++) d[mt][nt][q] = 0.0f;

    const int nStage = K >> 3;

    float4 av = *(const float4*)Ap;
    float4 wv = *(const float4*)Wp;

    // stash stage 0
    {
        float aa[4] = {av.x, av.y, av.z, av.w};
        float ww[4] = {wv.x, wv.y, wv.z, wv.w};
#pragma unroll
        for (int j = 0; j < 4; j++) {
            uint32_t h = f2tf32(aa[j]);
            AsH[0][ac + j][ar] = h;
            AsL[0][ac + j][ar] = f2tf32(aa[j] - __uint_as_float(h));
            uint32_t hw = f2tf32(ww[j]);
            BsH[0][br][bc + j] = hw;
            BsL[0][br][bc + j] = f2tf32(ww[j] - __uint_as_float(hw));
        }
    }
    __syncthreads();

    for (int s = 0; s < nStage; ++s) {
        const int buf = s & 1;
        if (s + 1 < nStage) {
            Ap += 8;
            Wp += (size_t)8 * N;
            av = *(const float4*)Ap;
            wv = *(const float4*)Wp;
        }

        // load A fragments (hi & lo) for both m-tiles
        uint32_t aH[2][4], aL[2][4];
#pragma unroll
        for (int mt = 0; mt < 2; mt++) {
            int m0 = wm + mt * 16;
            aH[mt][0] = AsH[buf][t4    ][m0 + g];
            aH[mt][1] = AsH[buf][t4    ][m0 + 8 + g];
            aH[mt][2] = AsH[buf][t4 + 4][m0 + g];
            aH[mt][3] = AsH[buf][t4 + 4][m0 + 8 + g];
            aL[mt][0] = AsL[buf][t4    ][m0 + g];
            aL[mt][1] = AsL[buf][t4    ][m0 + 8 + g];
            aL[mt][2] = AsL[buf][t4 + 4][m0 + g];
            aL[mt][3] = AsL[buf][t4 + 4][m0 + 8 + g];
        }

#pragma unroll
        for (int nt = 0; nt < 8; nt++) {
            int n0 = wn + nt * 8;
            uint32_t bH0 = BsH[buf][t4    ][n0 + g];
            uint32_t bH1 = BsH[buf][t4 + 4][n0 + g];
            uint32_t bL0 = BsL[buf][t4    ][n0 + g];
            uint32_t bL1 = BsL[buf][t4 + 4][n0 + g];
#pragma unroll
            for (int mt = 0; mt < 2; mt++) {
                MMA_TF32(d[mt][nt], aH[mt][0], aH[mt][1], aH[mt][2], aH[mt][3], bH0, bH1);
                MMA_TF32(d[mt][nt], aL[mt][0], aL[mt][1], aL[mt][2], aL[mt][3], bH0, bH1);
                MMA_TF32(d[mt][nt], aH[mt][0], aH[mt][1], aH[mt][2], aH[mt][3], bL0, bL1);
            }
        }

        if (s + 1 < nStage) {
            const int nb = (s + 1) & 1;
            float aa[4] = {av.x, av.y, av.z, av.w};
            float ww[4] = {wv.x, wv.y, wv.z, wv.w};
#pragma unroll
            for (int j = 0; j < 4; j++) {
                uint32_t h = f2tf32(aa[j]);
                AsH[nb][ac + j][ar] = h;
                AsL[nb][ac + j][ar] = f2tf32(aa[j] - __uint_as_float(h));
                uint32_t hw = f2tf32(ww[j]);
                BsH[nb][br][bc + j] = hw;
                BsL[nb][br][bc + j] = f2tf32(ww[j] - __uint_as_float(hw));
            }
            __syncthreads();
        }
    }

    // epilogue
    const int rayb = RAYBIAS ? (bm >> 7) * 128 : 0;
#pragma unroll
    for (int mt = 0; mt < 2; mt++) {
#pragma unroll
        for (int nt = 0; nt < 8; nt++) {
            int r0 = bm + wm + mt * 16 + g;
            int c0 = bn + wn + nt * 8 + 2 * t4;
            float b0v = RAYBIAS ? bias[rayb + c0]     : bias[c0];
            float b1v = RAYBIAS ? bias[rayb + c0 + 1] : bias[c0 + 1];
            float v00 = d[mt][nt][0] + b0v;
            float v01 = d[mt][nt][1] + b1v;
            float v10 = d[mt][nt][2] + b0v;
            float v11 = d[mt][nt][3] + b1v;
            if (RELU) {
                v00 = fmaxf(v00, 0.0f); v01 = fmaxf(v01, 0.0f);
                v10 = fmaxf(v10, 0.0f); v11 = fmaxf(v11, 0.0f);
            }
            float2 lo = make_float2(v00, v01);
            float2 hi = make_float2(v10, v11);
            *(float2*)&C[(size_t)r0 * N + c0]       = lo;
            *(float2*)&C[(size_t)(r0 + 8) * N + c0] = hi;
        }
    }
}

// ---------------- thin heads: sigma(256->1), [mu,sig](256->2), rgb(128->3) ----------------
__global__ void __launch_bounds__(256) heads_kernel(
    const float* __restrict__ X3, const float* __restrict__ H,
    const float* __restrict__ Ws, const float* __restrict__ bs,
    const float* __restrict__ Wm, const float* __restrict__ bm,
    const float* __restrict__ Wr, const float* __restrict__ br,
    float* __restrict__ RF)
{
    int gw = (blockIdx.x * 256 + threadIdx.x) >> 5;
    int lane = threadIdx.x & 31;
    if (gw >= NS) return;
    const bool hasM = (Wm != nullptr);
    const float* x = X3 + (size_t)gw * 256;
    float s0 = 0.0f, s1 = 0.0f, s2 = 0.0f;
#pragma unroll
    for (int i = 0; i < 8; i++) {
        int c = lane + 32 * i;
        float xv = x[c];
        s0 += xv * Ws[c];
        if (hasM) {
            s1 += xv * Wm[2 * c];
            s2 += xv * Wm[2 * c + 1];
        }
    }
    const float* h = H + (size_t)gw * 128;
    float r = 0.0f, g = 0.0f, b = 0.0f;
#pragma unroll
    for (int i = 0; i < 4; i++) {
        int c = lane + 32 * i;
        float hv = h[c];
        r += hv * Wr[3 * c];
        g += hv * Wr[3 * c + 1];
        b += hv * Wr[3 * c + 2];
    }
#pragma unroll
    for (int o = 16; o > 0; o >>= 1) {
        s0 += __shfl_down_sync(0xffffffffu, s0, o);
        s1 += __shfl_down_sync(0xffffffffu, s1, o);
        s2 += __shfl_down_sync(0xffffffffu, s2, o);
        r  += __shfl_down_sync(0xffffffffu, r, o);
        g  += __shfl_down_sync(0xffffffffu, g, o);
        b  += __shfl_down_sync(0xffffffffu, b, o);
    }
    if (lane == 0) {
        float* f = RF + (size_t)gw * 6;
        f[0] = r + br[0];
        f[1] = g + br[1];
        f[2] = b + br[2];
        f[3] = s0 + bs[0];
        if (hasM) {
            f[4] = s1 + bm[0];
            f[5] = s2 + bm[1];
        }
    }
}

// ---------------- coarse volume render + PDF ingredients ----------------
__global__ void vrender_coarse_kernel(float* __restrict__ out) {
    int r = blockIdx.x * blockDim.x + threadIdx.x;
    if (r >= NRAYS) return;
    float nrm = g_raynorm[r];
    float T = 1.0f, cr = 0.0f, cg = 0.0f, cb = 0.0f;
    for (int i = 0; i < 128; i++) {
        const float* f = g_rf + (size_t)(r * 128 + i) * 6;
        float t0 = 2.0f + 4.0f * ((float)i / 128.0f);
        float t1 = 2.0f + 4.0f * ((float)(i + 1) / 128.0f);
        float sr = sigmoidf_(f[0]);
        float sg = sigmoidf_(f[1]);
        float sb = sigmoidf_(f[2]);
        float sigma = fmaxf(f[3], 0.0f);
        float alpha = 1.0f - expf(-sigma * (t1 - t0) * nrm);
        float w = alpha * T;
        T *= (1.0f - alpha + 1e-10f);
        cr += w * sr; cg += w * sg; cb += w * sb;
        int si = r * 128 + i;
        g_weights[si] = w;
        float mu = sigmoidf_(f[4]);
        float ss = (sigmoidf_(f[5]) + 0.001f) * 2.0f;
        g_mus[si] = mu;
        g_smsig[si] = ss;
        float l = acdf_((0.0f - mu) / ss);
        g_lt[si] = l;
        g_pib[si] = acdf_((1.0f - mu) / ss) - l;
    }
    out[r * 3 + 0] = cr;
    out[r * 3 + 1] = cg;
    out[r * 3 + 2] = cb;
}

// ---------------- inverse-CDF fine sampling ----------------
__global__ void sample_pdf_kernel() {
    int r = blockIdx.x * blockDim.x + threadIdx.x;
    if (r >= NRAYS) return;
    float wl[128];
    float cdf[129];
    float sum = 0.0f;
    for (int i = 0; i < 128; i++) {
        float w = g_weights[r * 128 + i] + 1e-5f;
        wl[i] = w;
        sum += w;
    }
    float inv = 1.0f / sum;
    cdf[0] = 0.0f;
    float run = 0.0f;
    for (int i = 0; i < 128; i++) {
        run += wl[i] * inv;
        cdf[i + 1] = run;
    }
    int idx = 0;
    const float step = (1.0f - 1e-5f) / 128.0f;
    for (int i = 0; i < 129; i++) {
        float u = step * (float)i;
        while (idx < 127 && cdf[idx + 1] <= u) idx++;
        float pdfv = wl[idx] * inv;
        float frac = (u - cdf[idx]) / fmaxf(pdfv, 1e-10f);
        frac = fminf(fmaxf(frac, 0.0f), 1.0f);
        int si = r * 128 + idx;
        float p = g_lt[si] + frac * g_pib[si];
        p = fminf(fmaxf(p, 1e-5f), 1.0f - 1e-5f);
        float x = g_mus[si] + g_smsig[si] * 1.4142135623730951f * erfinvf(2.0f * p - 1.0f);
        x = fminf(fmaxf(x, 0.0f), 1.0f);
        float b0 = 2.0f + 4.0f * ((float)idx / 128.0f);
        float b1 = 2.0f + 4.0f * ((float)(idx + 1) / 128.0f);
        g_tfine[r * 129 + i] = b0 + x * (b1 - b0);
    }
}

// ---------------- fine volume render: rgb_f, depth_f, acc_f ----------------
__global__ void vrender_fine_kernel(float* __restrict__ out) {
    int r = blockIdx.x * blockDim.x + threadIdx.x;
    if (r >= NRAYS) return;
    float nrm = g_raynorm[r];
    float T = 1.0f, cr = 0.0f, cg = 0.0f, cb = 0.0f, dep = 0.0f, acc = 0.0f;
    for (int i = 0; i < 128; i++) {
        const float* f = g_rf + (size_t)(r * 128 + i) * 6;
        float t0 = g_tfine[r * 129 + i];
        float t1 = g_tfine[r * 129 + i + 1];
        float sr = sigmoidf_(f[0]);
        float sg = sigmoidf_(f[1]);
        float sb = sigmoidf_(f[2]);
        float sigma = fmaxf(f[3], 0.0f);
        float alpha = 1.0f - expf(-sigma * (t1 - t0) * nrm);
        float w = alpha * T;
        T *= (1.0f - alpha + 1e-10f);
        cr += w * sr; cg += w * sg; cb += w * sb;
        dep += w * 0.5f * (t0 + t1);
        acc += w;
    }
    out[6144 + r * 3 + 0] = cr;
    out[6144 + r * 3 + 1] = cg;
    out[6144 + r * 3 + 2] = cb;
    out[12288 + r] = dep;
    out[14336 + r] = acc;
}

// ---------------- host orchestration ----------------
extern "C" void kernel_launch(void* const* d_in, const int* in_sizes, int n_in,
                              void* d_out, int out_size)
{
    (void)out_size;
    const float* ro = (const float*)d_in[0];
    const float* rd = (const float*)d_in[1];
    const float* rr = (const float*)d_in[2];

    bool sigOrder = (n_in > 15 && in_sizes[15] == 512);
    int fb = sigOrder ? 17 : 15;
    int mb = sigOrder ? 15 : 27;

    const float* cW0 = (const float*)d_in[3];
    const float* cb0 = (const float*)d_in[4];
    const float* cWh = (const float*)d_in[5];
    const float* cbh = (const float*)d_in[6];
    const float* cWs = (const float*)d_in[7];
    const float* cbs = (const float*)d_in[8];
    const float* cWb = (const float*)d_in[9];
    const float* cbb = (const float*)d_in[10];
    const float* cWd = (const float*)d_in[11];
    const float* cbd = (const float*)d_in[12];
    const float* cWr = (const float*)d_in[13];
    const float* cbr = (const float*)d_in[14];
    const float* cWm = (const float*)d_in[mb];
    const float* cbm = (const float*)d_in[mb + 1];
    const float* fW0 = (const float*)d_in[fb + 0];
    const float* fb0 = (const float*)d_in[fb + 1];
    const float* fWh = (const float*)d_in[fb + 2];
    const float* fbh = (const float*)d_in[fb + 3];
    const float* fWs = (const float*)d_in[fb + 4];
    const float* fbs = (const float*)d_in[fb + 5];
    const float* fWb = (const float*)d_in[fb + 6];
    const float* fbb = (const float*)d_in[fb + 7];
    const float* fWd = (const float*)d_in[fb + 8];
    const float* fbd = (const float*)d_in[fb + 9];
    const float* fWr = (const float*)d_in[fb + 10];
    const float* fbr = (const float*)d_in[fb + 11];

    float *p_enc, *p_x0, *p_x1, *p_h, *p_rf, *p_raybias, *p_tfine;
    cudaGetSymbolAddress((void**)&p_enc, g_enc);
    cudaGetSymbolAddress((void**)&p_x0, g_x0);
    cudaGetSymbolAddress((void**)&p_x1, g_x1);
    cudaGetSymbolAddress((void**)&p_h, g_h);
    cudaGetSymbolAddress((void**)&p_rf, g_rf);
    cudaGetSymbolAddress((void**)&p_raybias, g_raybias);
    cudaGetSymbolAddress((void**)&p_tfine, g_tfine);

    float* out = (float*)d_out;
    const dim3 gWide(NS / 128, 2);   // N=256 layers
    const dim3 gNarrow(NS / 128, 1); // N=128 layer

    ray_setup_kernel<<<(NRAYS + 127) / 128, 128>>>(rd);

    // ================= coarse pass =================
    ipe_kernel<<<NS / 128, 128>>>(ro, rd, rr, nullptr);
    ray_bias_kernel<<<NRAYS, 128>>>(cWd, cbd);
    sgemm_tc<true, false><<<gWide, 256>>>(p_enc, cW0, cb0, p_x0, 96, 256);
    sgemm_tc<true, false><<<gWide, 256>>>(p_x0, cWh,          cbh,       p_x1, 256, 256);
    sgemm_tc<true, false><<<gWide, 256>>>(p_x1, cWh + 65536,  cbh + 256, p_x0, 256, 256);
    sgemm_tc<true, false><<<gWide, 256>>>(p_x0, cWh + 131072, cbh + 512, p_x1, 256, 256);
    sgemm_tc<false, false><<<gWide, 256>>>(p_x1, cWb, cbb, p_x0, 256, 256);
    sgemm_tc<true, true><<<gNarrow, 256>>>(p_x0, cWd, p_raybias, p_h, 256, 128);
    heads_kernel<<<NS / 8, 256>>>(p_x1, p_h, cWs, cbs, cWm, cbm, cWr, cbr, p_rf);
    vrender_coarse_kernel<<<(NRAYS + 127) / 128, 128>>>(out);
    sample_pdf_kernel<<<(NRAYS + 127) / 128, 128>>>();

    // ================= fine pass =================
    ipe_kernel<<<NS / 128, 128>>>(ro, rd, rr, p_tfine);
    ray_bias_kernel<<<NRAYS, 128>>>(fWd, fbd);
    sgemm_tc<true, false><<<gWide, 256>>>(p_enc, fW0, fb0, p_x0, 96, 256);
    sgemm_tc<true, false><<<gWide, 256>>>(p_x0, fWh,          fbh,       p_x1, 256, 256);
    sgemm_tc<true, false><<<gWide, 256>>>(p_x1, fWh + 65536,  fbh + 256, p_x0, 256, 256);
    sgemm_tc<true, false><<<gWide, 256>>>(p_x0, fWh + 131072, fbh + 512, p_x1, 256, 256);
    sgemm_tc<false, false><<<gWide, 256>>>(p_x1, fWb, fbb, p_x0, 256, 256);
    sgemm_tc<true, true><<<gNarrow, 256>>>(p_x0, fWd, p_raybias, p_h, 256, 128);
    heads_kernel<<<NS / 8, 256>>>(p_x1, p_h, fWs, fbs, nullptr, nullptr, fWr, fbr, p_rf);
    vrender_fine_kernel<<<(NRAYS + 127) / 128, 128>>>(out);
}